// round 14
// baseline (speedup 1.0000x reference)
#include <cuda_runtime.h>
#include <math.h>
#include <stdint.h>

#define Bb 2
#define Ss 1024
#define Tt 2048
#define Dd 2048
#define Ll 4
#define NE 16
#define Hh 16
#define DHh 128
#define CAPe 153

typedef unsigned long long u64;

// ---------------- tf32 helpers ----------------------------------------------
__device__ __forceinline__ float tf32r(float x) {
    uint32_t u; asm("cvt.rna.tf32.f32 %0, %1;" : "=r"(u) : "f"(x));
    return __uint_as_float(u);
}
__device__ __forceinline__ void mma8(float* d, const uint32_t* a, const uint32_t* b) {
    asm("mma.sync.aligned.m16n8k8.row.col.f32.tf32.tf32.f32 "
        "{%0,%1,%2,%3}, {%4,%5,%6,%7}, {%8,%9}, {%0,%1,%2,%3};"
        : "+f"(d[0]), "+f"(d[1]), "+f"(d[2]), "+f"(d[3])
        : "r"(a[0]), "r"(a[1]), "r"(a[2]), "r"(a[3]), "r"(b[0]), "r"(b[1]));
}

// ---- dense GEMM smem (stride 36) --------------------------------------------
#define AS_HI 0
#define AS_LO 4608
#define WS_HI 9216
#define WS_LO 11520
#define MMA_SMEM_FLOATS 13824
#define MMA_SMEM_BYTES  (MMA_SMEM_FLOATS * 4)

// ---- MoE BM=64 smem ---------------------------------------------------------
#define MA_HI 0
#define MA_LO 2304
#define MW_HI 4608
#define MW_LO 6912
#define MOE_SMEM_FLOATS 9216
#define MOE_SMEM_BYTES  (MOE_SMEM_FLOATS * 4)

// ---- attention smem ---------------------------------------------------------
#define QHI 0
#define QLO 4224
#define KVHI 8448
#define KVLO 13056
#define SC_  17664
#define PHI  18816
#define PLO  19968
#define MS   21120
#define LS   21152
#define CS   21184
#define ATTN_SMEM_FLOATS 21216
#define ATTN_SMEM_BYTES  (ATTN_SMEM_FLOATS * 4)

// ---------------- scratch ----------------------------------------------------
__device__ float g_x[Tt * Dd];
__device__ float g_xn[Tt * Dd];
__device__ float g_qkv[Tt * 3 * Dd];
__device__ float g_attn[Tt * Dd];
__device__ int   g_expert[Tt];
__device__ float g_prob[Tt];
__device__ float g_probsum[NE];
__device__ int   g_tok[NE * CAPe];
__device__ int   g_cnt[NE];
__device__ float g_aux;

__global__ void k_init() { g_aux = 0.0f; }
__global__ void k_zero16() { if (threadIdx.x < NE) g_probsum[threadIdx.x] = 0.0f; }

// ---------------- embedding gather ------------------------------------------
__global__ void k_embed(const int* __restrict__ tokens, const float* __restrict__ emb) {
    int idx = blockIdx.x * 256 + threadIdx.x;
    int t = idx / Dd;
    int d = idx % Dd;
    g_x[idx] = emb[(size_t)tokens[t] * Dd + d];
}

// ---------------- layernorm -------------------------------------------------
__global__ void k_ln(const float* __restrict__ gamma, const float* __restrict__ beta) {
    int t = blockIdx.x;
    const float* row = g_x + (size_t)t * Dd;
    float s = 0.f, s2 = 0.f;
    for (int d = threadIdx.x; d < Dd; d += 256) {
        float v = row[d];
        s += v; s2 += v * v;
    }
    #pragma unroll
    for (int o = 16; o; o >>= 1) {
        s  += __shfl_xor_sync(0xffffffffu, s, o);
        s2 += __shfl_xor_sync(0xffffffffu, s2, o);
    }
    __shared__ float shs[8], shs2[8];
    __shared__ float smu, srstd;
    int w = threadIdx.x >> 5, ln = threadIdx.x & 31;
    if (ln == 0) { shs[w] = s; shs2[w] = s2; }
    __syncthreads();
    if (threadIdx.x == 0) {
        float a = 0.f, b2 = 0.f;
        #pragma unroll
        for (int i = 0; i < 8; i++) { a += shs[i]; b2 += shs2[i]; }
        float m = a / (float)Dd;
        float var = b2 / (float)Dd - m * m;
        smu = m;
        srstd = rsqrtf(var + 1e-5f);
    }
    __syncthreads();
    float mu = smu, rstd = srstd;
    for (int d = threadIdx.x; d < Dd; d += 256)
        g_xn[(size_t)t * Dd + d] = (row[d] - mu) * rstd * gamma[d] + beta[d];
}

// ---------------- staging helper --------------------------------------------
__device__ __forceinline__ void split_store(float* sm, int hi_off, int lo_off,
                                            int pos, float4 v) {
    float4 h, l;
    h.x = tf32r(v.x); l.x = tf32r(v.x - h.x);
    h.y = tf32r(v.y); l.y = tf32r(v.y - h.y);
    h.z = tf32r(v.z); l.z = tf32r(v.z - h.z);
    h.w = tf32r(v.w); l.w = tf32r(v.w - h.w);
    *(float4*)(sm + hi_off + pos) = h;
    *(float4*)(sm + lo_off + pos) = l;
}

// ---------------- GEMM mma chunk (BK=32, warp 32x32) -------------------------
__device__ __forceinline__ void mma_chunk(const float* sm, int wr, int wc,
                                          int grp, int qid, float acc[2][4][4]) {
    #pragma unroll
    for (int ks = 0; ks < 4; ks++) {
        int kc = ks * 8;
        uint32_t ahi[2][4], alo[2][4], bhi[4][2], blo[4][2];
        #pragma unroll
        for (int mi = 0; mi < 2; mi++) {
            int rb = wr * 32 + mi * 16;
            int i00 = (rb + grp) * 36 + kc + qid;
            int i10 = (rb + grp + 8) * 36 + kc + qid;
            ahi[mi][0] = *(const uint32_t*)(sm + AS_HI + i00);
            ahi[mi][1] = *(const uint32_t*)(sm + AS_HI + i10);
            ahi[mi][2] = *(const uint32_t*)(sm + AS_HI + i00 + 4);
            ahi[mi][3] = *(const uint32_t*)(sm + AS_HI + i10 + 4);
            alo[mi][0] = *(const uint32_t*)(sm + AS_LO + i00);
            alo[mi][1] = *(const uint32_t*)(sm + AS_LO + i10);
            alo[mi][2] = *(const uint32_t*)(sm + AS_LO + i00 + 4);
            alo[mi][3] = *(const uint32_t*)(sm + AS_LO + i10 + 4);
        }
        #pragma unroll
        for (int ni = 0; ni < 4; ni++) {
            int nb = wc * 32 + ni * 8;
            int i0 = (nb + grp) * 36 + kc + qid;
            bhi[ni][0] = *(const uint32_t*)(sm + WS_HI + i0);
            bhi[ni][1] = *(const uint32_t*)(sm + WS_HI + i0 + 4);
            blo[ni][0] = *(const uint32_t*)(sm + WS_LO + i0);
            blo[ni][1] = *(const uint32_t*)(sm + WS_LO + i0 + 4);
        }
        #pragma unroll
        for (int mi = 0; mi < 2; mi++)
            #pragma unroll
            for (int ni = 0; ni < 4; ni++)
                mma8(acc[mi][ni], ahi[mi], bhi[ni]);
        #pragma unroll
        for (int mi = 0; mi < 2; mi++)
            #pragma unroll
            for (int ni = 0; ni < 4; ni++)
                mma8(acc[mi][ni], ahi[mi], blo[ni]);
        #pragma unroll
        for (int mi = 0; mi < 2; mi++)
            #pragma unroll
            for (int ni = 0; ni < 4; ni++)
                mma8(acc[mi][ni], alo[mi], bhi[ni]);
    }
}

// ---------------- dense GEMM: 3 CTAs/SM, no reg prefetch ---------------------
__global__ void __launch_bounds__(256, 3)
k_gemm_mma(const float* __restrict__ A, const float* __restrict__ W,
           const float* __restrict__ bias, const float* __restrict__ res,
           float* __restrict__ C, int N, int K) {
    extern __shared__ float sm[];
    int tid = threadIdx.x, wid = tid >> 5, lane = tid & 31;
    int grp = lane >> 2, qid = lane & 3;
    int wr = wid & 3, wc = wid >> 2;
    int bm = blockIdx.y * 128, bn = blockIdx.x * 64;

    float acc[2][4][4];
    #pragma unroll
    for (int mi = 0; mi < 2; mi++)
        #pragma unroll
        for (int ni = 0; ni < 4; ni++)
            #pragma unroll
            for (int j = 0; j < 4; j++) acc[mi][ni][j] = 0.f;

    int rA0 = tid >> 3,           cA0 = (tid & 7) * 4;
    int rA1 = (tid + 256) >> 3;
    int rA2 = (tid + 512) >> 3;
    int rA3 = (tid + 768) >> 3;
    int posA0 = rA0 * 36 + cA0, posA1 = rA1 * 36 + cA0;
    int posA2 = rA2 * 36 + cA0, posA3 = rA3 * 36 + cA0;

    const float* ApA0 = A + (size_t)(bm + rA0) * K + cA0;
    const float* ApA1 = A + (size_t)(bm + rA1) * K + cA0;
    const float* ApA2 = A + (size_t)(bm + rA2) * K + cA0;
    const float* ApA3 = A + (size_t)(bm + rA3) * K + cA0;
    const float* WpW0 = W + (size_t)(bn + rA0) * K + cA0;
    const float* WpW1 = W + (size_t)(bn + rA1) * K + cA0;

    int nch = K / 32;
    for (int c = 0; c < nch; c++) {
        int k0 = c * 32;
        split_store(sm, AS_HI, AS_LO, posA0, *(const float4*)(ApA0 + k0));
        split_store(sm, AS_HI, AS_LO, posA1, *(const float4*)(ApA1 + k0));
        split_store(sm, AS_HI, AS_LO, posA2, *(const float4*)(ApA2 + k0));
        split_store(sm, AS_HI, AS_LO, posA3, *(const float4*)(ApA3 + k0));
        split_store(sm, WS_HI, WS_LO, posA0, *(const float4*)(WpW0 + k0));
        split_store(sm, WS_HI, WS_LO, posA1, *(const float4*)(WpW1 + k0));
        __syncthreads();
        mma_chunk(sm, wr, wc, grp, qid, acc);
        __syncthreads();
    }

    #pragma unroll
    for (int mi = 0; mi < 2; mi++) {
        #pragma unroll
        for (int ni = 0; ni < 4; ni++) {
            int r0 = bm + wr * 32 + mi * 16 + grp;
            int r1 = r0 + 8;
            int cc = bn + wc * 32 + ni * 8 + qid * 2;
            float b0 = bias[cc], b1 = bias[cc + 1];
            float v0 = acc[mi][ni][0] + b0, v1 = acc[mi][ni][1] + b1;
            float v2 = acc[mi][ni][2] + b0, v3 = acc[mi][ni][3] + b1;
            if (res) {
                v0 += res[(size_t)r0 * N + cc];
                v1 += res[(size_t)r0 * N + cc + 1];
                v2 += res[(size_t)r1 * N + cc];
                v3 += res[(size_t)r1 * N + cc + 1];
            }
            C[(size_t)r0 * N + cc]     = v0;
            C[(size_t)r0 * N + cc + 1] = v1;
            C[(size_t)r1 * N + cc]     = v2;
            C[(size_t)r1 * N + cc + 1] = v3;
        }
    }
}

// ---------------- MoE GEMM, BM=64, 3 CTAs/SM, no reg prefetch ----------------
__global__ void __launch_bounds__(256, 3)
k_moe_mma(const float* __restrict__ w_exp, const float* __restrict__ b_exp) {
    int e = blockIdx.z;
    int cnt = g_cnt[e];
    int row0 = blockIdx.y * 64;
    if (row0 >= cnt) return;
    int bn = blockIdx.x * 64;

    extern __shared__ float sm[];
    __shared__ int   toks[64];
    __shared__ float pb[64];
    int tid = threadIdx.x, wid = tid >> 5, lane = tid & 31;
    int grp = lane >> 2, qid = lane & 3;
    int wr = wid & 3, wc = wid >> 2;

    if (tid < 64) {
        int s = row0 + tid;
        if (s < cnt) {
            int t = g_tok[e * CAPe + s];
            toks[tid] = t;
            pb[tid] = g_prob[t];
        } else {
            toks[tid] = -1;
            pb[tid] = 0.f;
        }
    }
    __syncthreads();

    float acc[4][4];
    #pragma unroll
    for (int ni = 0; ni < 4; ni++)
        #pragma unroll
        for (int j = 0; j < 4; j++) acc[ni][j] = 0.f;

    int rS0 = tid >> 3,          cS0 = (tid & 7) * 4;
    int rS1 = (tid + 256) >> 3;
    int posS0 = rS0 * 36 + cS0, posS1 = rS1 * 36 + cS0;
    int tA0 = toks[rS0], tA1 = toks[rS1];

    const float* Ap0 = (tA0 >= 0) ? (g_xn + (size_t)tA0 * Dd + cS0) : nullptr;
    const float* Ap1 = (tA1 >= 0) ? (g_xn + (size_t)tA1 * Dd + cS0) : nullptr;
    const float* Wb = w_exp + (size_t)e * Dd * Dd + (size_t)bn * Dd;
    const float* Wp0 = Wb + (size_t)rS0 * Dd + cS0;
    const float* Wp1 = Wb + (size_t)rS1 * Dd + cS0;

    const int nch = Dd / 32;
    float4 z4 = make_float4(0.f, 0.f, 0.f, 0.f);

    for (int c = 0; c < nch; c++) {
        int k0 = c * 32;
        split_store(sm, MA_HI, MA_LO, posS0, Ap0 ? *(const float4*)(Ap0 + k0) : z4);
        split_store(sm, MA_HI, MA_LO, posS1, Ap1 ? *(const float4*)(Ap1 + k0) : z4);
        split_store(sm, MW_HI, MW_LO, posS0, *(const float4*)(Wp0 + k0));
        split_store(sm, MW_HI, MW_LO, posS1, *(const float4*)(Wp1 + k0));
        __syncthreads();
        #pragma unroll
        for (int ks = 0; ks < 4; ks++) {
            int kc = ks * 8;
            uint32_t ah[4], al[4], bh_[4][2], bl_[4][2];
            {
                int i00 = (wr * 16 + grp) * 36 + kc + qid;
                int i10 = i00 + 8 * 36;
                ah[0] = *(const uint32_t*)(sm + MA_HI + i00);
                ah[1] = *(const uint32_t*)(sm + MA_HI + i10);
                ah[2] = *(const uint32_t*)(sm + MA_HI + i00 + 4);
                ah[3] = *(const uint32_t*)(sm + MA_HI + i10 + 4);
                al[0] = *(const uint32_t*)(sm + MA_LO + i00);
                al[1] = *(const uint32_t*)(sm + MA_LO + i10);
                al[2] = *(const uint32_t*)(sm + MA_LO + i00 + 4);
                al[3] = *(const uint32_t*)(sm + MA_LO + i10 + 4);
            }
            #pragma unroll
            for (int ni = 0; ni < 4; ni++) {
                int i0 = (wc * 32 + ni * 8 + grp) * 36 + kc + qid;
                bh_[ni][0] = *(const uint32_t*)(sm + MW_HI + i0);
                bh_[ni][1] = *(const uint32_t*)(sm + MW_HI + i0 + 4);
                bl_[ni][0] = *(const uint32_t*)(sm + MW_LO + i0);
                bl_[ni][1] = *(const uint32_t*)(sm + MW_LO + i0 + 4);
            }
            #pragma unroll
            for (int ni = 0; ni < 4; ni++) mma8(acc[ni], ah, bh_[ni]);
            #pragma unroll
            for (int ni = 0; ni < 4; ni++) mma8(acc[ni], ah, bl_[ni]);
            #pragma unroll
            for (int ni = 0; ni < 4; ni++) mma8(acc[ni], al, bh_[ni]);
        }
        __syncthreads();
    }

    const float* be = b_exp + (size_t)e * Dd;
    int lr0 = wr * 16 + grp;
    int lr1 = lr0 + 8;
    int s0 = row0 + lr0, s1 = row0 + lr1;
    #pragma unroll
    for (int ni = 0; ni < 4; ni++) {
        int cc = bn + wc * 32 + ni * 8 + qid * 2;
        float b0 = be[cc], b1 = be[cc + 1];
        if (s0 < cnt) {
            int t = toks[lr0]; float p = pb[lr0];
            g_x[(size_t)t * Dd + cc]     += p * (acc[ni][0] + b0);
            g_x[(size_t)t * Dd + cc + 1] += p * (acc[ni][1] + b1);
        }
        if (s1 < cnt) {
            int t = toks[lr1]; float p = pb[lr1];
            g_x[(size_t)t * Dd + cc]     += p * (acc[ni][2] + b0);
            g_x[(size_t)t * Dd + cc + 1] += p * (acc[ni][3] + b1);
        }
    }
}

// ---------------- attention via tf32 mma (R12 config) ------------------------
__global__ void __launch_bounds__(256, 2) k_attn_mma() {
    extern __shared__ float sm[];
    int bh = blockIdx.x;
    int b = bh >> 4, h = bh & 15;
    int q0 = blockIdx.y * 32;
    int tid = threadIdx.x, wid = tid >> 5, lane = tid & 31;
    int grp = lane >> 2, qid = lane & 3;
    int wr = wid & 1, wc = wid >> 1;
    int r8 = tid >> 3, dp = tid & 7;

    const float scale = 0.08838834764831845f;

    if (tid < 32) { sm[MS + tid] = -1e30f; sm[LS + tid] = 0.f; }

    {
        const float* src = &g_qkv[(size_t)(b * Ss + q0 + r8) * (3 * Dd) + h * DHh + dp * 16];
        int pos = r8 * 132 + dp * 16;
        #pragma unroll
        for (int j = 0; j < 4; j++)
            split_store(sm, QHI, QLO, pos + j * 4, *(const float4*)(src + j * 4));
    }

    float accO[4][4];
    #pragma unroll
    for (int ni = 0; ni < 4; ni++)
        #pragma unroll
        for (int j = 0; j < 4; j++) accO[ni][j] = 0.f;

    for (int kb = 0; kb < Ss; kb += 32) {
        __syncthreads();
        {
            const float* src = &g_qkv[(size_t)(b * Ss + kb + r8) * (3 * Dd) + Dd + h * DHh + dp * 16];
            int pos = r8 * 132 + dp * 16;
            #pragma unroll
            for (int j = 0; j < 4; j++)
                split_store(sm, KVHI, KVLO, pos + j * 4, *(const float4*)(src + j * 4));
        }
        __syncthreads();

        {
            float accS[4] = {0.f, 0.f, 0.f, 0.f};
            int arow = (wr * 16 + grp) * 132 + qid;
            int brow = (wc * 8 + grp) * 132 + qid;
            #pragma unroll
            for (int kc = 0; kc < 128; kc += 8) {
                uint32_t ah[4], al[4], bh_[2], bl_[2];
                ah[0] = __float_as_uint(sm[QHI + arow + kc]);
                ah[1] = __float_as_uint(sm[QHI + arow + 8 * 132 + kc]);
                ah[2] = __float_as_uint(sm[QHI + arow + kc + 4]);
                ah[3] = __float_as_uint(sm[QHI + arow + 8 * 132 + kc + 4]);
                al[0] = __float_as_uint(sm[QLO + arow + kc]);
                al[1] = __float_as_uint(sm[QLO + arow + 8 * 132 + kc]);
                al[2] = __float_as_uint(sm[QLO + arow + kc + 4]);
                al[3] = __float_as_uint(sm[QLO + arow + 8 * 132 + kc + 4]);
                bh_[0] = __float_as_uint(sm[KVHI + brow + kc]);
                bh_[1] = __float_as_uint(sm[KVHI + brow + kc + 4]);
                bl_[0] = __float_as_uint(sm[KVLO + brow + kc]);
                bl_[1] = __float_as_uint(sm[KVLO + brow + kc + 4]);
                mma8(accS, ah, bh_);
                mma8(accS, ah, bl_);
                mma8(accS, al, bh_);
            }
            int sr = wr * 16 + grp, scc = wc * 8 + qid * 2;
            sm[SC_ + sr * 36 + scc]           = accS[0] * scale;
            sm[SC_ + sr * 36 + scc + 1]       = accS[1] * scale;
            sm[SC_ + (sr + 8) * 36 + scc]     = accS[2] * scale;
            sm[SC_ + (sr + 8) * 36 + scc + 1] = accS[3] * scale;
        }
        __syncthreads();

        {
            const float* src = &g_qkv[(size_t)(b * Ss + kb + r8) * (3 * Dd) + 2 * Dd + h * DHh + dp * 16];
            #pragma unroll
            for (int j = 0; j < 4; j++) {
                float4 v = *(const float4*)(src + j * 4);
                float vv[4] = {v.x, v.y, v.z, v.w};
                #pragma unroll
                for (int c2 = 0; c2 < 4; c2++) {
                    int d = dp * 16 + j * 4 + c2;
                    int kvp = (r8 + ((d >> 4) << 2)) & 31;
                    float hv = tf32r(vv[c2]);
                    sm[KVHI + d * 36 + kvp] = hv;
                    sm[KVLO + d * 36 + kvp] = tf32r(vv[c2] - hv);
                }
            }
        }

        {
            int q = r8;
            float sc4[4];
            float mx = -1e30f;
            #pragma unroll
            for (int c2 = 0; c2 < 4; c2++) {
                sc4[c2] = sm[SC_ + q * 36 + dp * 4 + c2];
                mx = fmaxf(mx, sc4[c2]);
            }
            #pragma unroll
            for (int o = 1; o < 8; o <<= 1)
                mx = fmaxf(mx, __shfl_xor_sync(0xffffffffu, mx, o));
            float mold = sm[MS + q], lold = sm[LS + q];
            float nm = fmaxf(mold, mx);
            float lsum = 0.f;
            #pragma unroll
            for (int c2 = 0; c2 < 4; c2++) {
                float p = __expf(sc4[c2] - nm);
                lsum += p;
                float hv = tf32r(p);
                sm[PHI + q * 36 + dp * 4 + c2] = hv;
                sm[PLO + q * 36 + dp * 4 + c2] = tf32r(p - hv);
            }
            #pragma unroll
            for (int o = 1; o < 8; o <<= 1)
                lsum += __shfl_xor_sync(0xffffffffu, lsum, o);
            if (dp == 0) {
                float corr = __expf(mold - nm);
                sm[MS + q] = nm;
                sm[LS + q] = lold * corr + lsum;
                sm[CS + q] = corr;
            }
        }
        __syncthreads();

        {
            float c0 = sm[CS + wr * 16 + grp];
            float c1 = sm[CS + wr * 16 + grp + 8];
            #pragma unroll
            for (int ni = 0; ni < 4; ni++) {
                accO[ni][0] *= c0; accO[ni][1] *= c0;
                accO[ni][2] *= c1; accO[ni][3] *= c1;
            }
            int arow = (wr * 16 + grp) * 36 + qid;
            #pragma unroll
            for (int kc = 0; kc < 32; kc += 8) {
                uint32_t ah[4], al[4];
                ah[0] = __float_as_uint(sm[PHI + arow + kc]);
                ah[1] = __float_as_uint(sm[PHI + arow + 8 * 36 + kc]);
                ah[2] = __float_as_uint(sm[PHI + arow + kc + 4]);
                ah[3] = __float_as_uint(sm[PHI + arow + 8 * 36 + kc + 4]);
                al[0] = __float_as_uint(sm[PLO + arow + kc]);
                al[1] = __float_as_uint(sm[PLO + arow + 8 * 36 + kc]);
                al[2] = __float_as_uint(sm[PLO + arow + kc + 4]);
                al[3] = __float_as_uint(sm[PLO + arow + 8 * 36 + kc + 4]);
                #pragma unroll
                for (int ni = 0; ni < 4; ni++) {
                    int n = wc * 32 + ni * 8 + grp;
                    int off = (n >> 4) << 2;
                    int k0i = (kc + qid + off) & 31;
                    int k1i = (kc + qid + 4 + off) & 31;
                    uint32_t bh_[2], bl_[2];
                    bh_[0] = __float_as_uint(sm[KVHI + n * 36 + k0i]);
                    bh_[1] = __float_as_uint(sm[KVHI + n * 36 + k1i]);
                    bl_[0] = __float_as_uint(sm[KVLO + n * 36 + k0i]);
                    bl_[1] = __float_as_uint(sm[KVLO + n * 36 + k1i]);
                    mma8(accO[ni], ah, bh_);
                    mma8(accO[ni], ah, bl_);
                    mma8(accO[ni], al, bh_);
                }
            }
        }
    }

    {
        float li0 = 1.f / sm[LS + wr * 16 + grp];
        float li1 = 1.f / sm[LS + wr * 16 + grp + 8];
        size_t t0 = (size_t)(b * Ss + q0 + wr * 16 + grp) * Dd + h * DHh;
        size_t t1 = (size_t)(b * Ss + q0 + wr * 16 + grp + 8) * Dd + h * DHh;
        #pragma unroll
        for (int ni = 0; ni < 4; ni++) {
            int col = wc * 32 + ni * 8 + qid * 2;
            g_attn[t0 + col]     = accO[ni][0] * li0;
            g_attn[t0 + col + 1] = accO[ni][1] * li0;
            g_attn[t1 + col]     = accO[ni][2] * li1;
            g_attn[t1 + col + 1] = accO[ni][3] * li1;
        }
    }
}

// ---------------- gate ------------------------------------------------------
__global__ void k_gate(const float* __restrict__ wg) {
    int warp = threadIdx.x >> 5;
    int lane = threadIdx.x & 31;
    int t = blockIdx.x * 8 + warp;
    __shared__ float bsum[NE];
    if (threadIdx.x < NE) bsum[threadIdx.x] = 0.f;
    __syncthreads();

    float lg[16];
    #pragma unroll
    for (int e = 0; e < 16; e++) lg[e] = 0.f;
    const float* row = g_xn + (size_t)t * Dd;
    for (int d = lane; d < Dd; d += 32) {
        float x = row[d];
        const float* w = wg + (size_t)d * NE;
        #pragma unroll
        for (int e = 0; e < 16; e++) lg[e] += x * w[e];
    }
    #pragma unroll
    for (int e = 0; e < 16; e++)
        #pragma unroll
        for (int o = 16; o; o >>= 1) lg[e] += __shfl_xor_sync(0xffffffffu, lg[e], o);

    float mx = lg[0];
    #pragma unroll
    for (int e = 1; e < 16; e++) mx = fmaxf(mx, lg[e]);
    float pe[16]; float se = 0.f;
    #pragma unroll
    for (int e = 0; e < 16; e++) { pe[e] = __expf(lg[e] - mx); se += pe[e]; }
    float inv = 1.f / se;

    if (lane == 0) {
        int be = 0; float bl = lg[0];
        #pragma unroll
        for (int e = 1; e < 16; e++) if (lg[e] > bl) { bl = lg[e]; be = e; }
        g_expert[t] = be;
        g_prob[t] = pe[be] * inv;
        #pragma unroll
        for (int e = 0; e < 16; e++) atomicAdd(&bsum[e], pe[e] * inv);
    }
    __syncthreads();
    if (threadIdx.x < NE) atomicAdd(&g_probsum[threadIdx.x], bsum[threadIdx.x]);
}

// ---------------- routing ---------------------------------------------------
__global__ void k_route() {
    __shared__ int sh_e[Tt];
    __shared__ int cnts[256][NE];
    __shared__ int tot[NE];
    int tid = threadIdx.x;
    for (int i = tid; i < Tt; i += 256) sh_e[i] = g_expert[i];
    #pragma unroll
    for (int e = 0; e < NE; e++) cnts[tid][e] = 0;
    __syncthreads();
    for (int i = 0; i < 8; i++) {
        int e = sh_e[tid * 8 + i];
        cnts[tid][e]++;
    }
    __syncthreads();
    if (tid < NE) {
        int run = 0;
        for (int i = 0; i < 256; i++) {
            int c = cnts[i][tid];
            cnts[i][tid] = run;
            run += c;
        }
        tot[tid] = run;
        g_cnt[tid] = (run < CAPe) ? run : CAPe;
    }
    __syncthreads();
    for (int i = 0; i < 8; i++) {
        int t = tid * 8 + i;
        int e = sh_e[t];
        int r = cnts[tid][e]++;
        if (r < CAPe) g_tok[e * CAPe + r] = t;
    }
    if (tid == 0) {
        float a = 0.f;
        for (int e = 0; e < NE; e++) a += (float)tot[e] * g_probsum[e];
        g_aux += a * ((float)NE / ((float)Tt * (float)Tt));
    }
}

// ---------------- output ----------------------------------------------------
__global__ void k_out(float* __restrict__ out, int n) {
    int idx = blockIdx.x * 256 + threadIdx.x;
    if (idx < n) {
        if (idx < Tt * Dd) out[idx] = g_x[idx];
        else out[idx] = g_aux;
    }
}

// ---------------- launch ----------------------------------------------------
extern "C" void kernel_launch(void* const* d_in, const int* in_sizes, int n_in,
                              void* d_out, int out_size) {
    const int*   tokens = (const int*)d_in[0];
    const float* emb    = (const float*)d_in[1];
    const float* w_qkv  = (const float*)d_in[2];
    const float* b_qkv  = (const float*)d_in[3];
    const float* w_out  = (const float*)d_in[4];
    const float* b_out  = (const float*)d_in[5];
    const float* attn_g = (const float*)d_in[6];
    const float* attn_b = (const float*)d_in[7];
    const float* moe_g  = (const float*)d_in[8];
    const float* moe_b  = (const float*)d_in[9];
    const float* w_gate = (const float*)d_in[10];
    const float* w_exp  = (const float*)d_in[11];
    const float* b_exp  = (const float*)d_in[12];

    float *px, *pxn, *pqkv, *pattn;
    cudaGetSymbolAddress((void**)&px, g_x);
    cudaGetSymbolAddress((void**)&pxn, g_xn);
    cudaGetSymbolAddress((void**)&pqkv, g_qkv);
    cudaGetSymbolAddress((void**)&pattn, g_attn);

    cudaFuncSetAttribute(k_gemm_mma, cudaFuncAttributeMaxDynamicSharedMemorySize, MMA_SMEM_BYTES);
    cudaFuncSetAttribute(k_moe_mma, cudaFuncAttributeMaxDynamicSharedMemorySize, MOE_SMEM_BYTES);
    cudaFuncSetAttribute(k_attn_mma, cudaFuncAttributeMaxDynamicSharedMemorySize, ATTN_SMEM_BYTES);

    k_init<<<1, 1>>>();
    k_embed<<<(Tt * Dd) / 256, 256>>>(tokens, emb);

    for (int l = 0; l < Ll; l++) {
        k_ln<<<Tt, 256>>>(attn_g + (size_t)l * Dd, attn_b + (size_t)l * Dd);
        k_gemm_mma<<<dim3((3 * Dd) / 64, Tt / 128), 256, MMA_SMEM_BYTES>>>(
            pxn, w_qkv, b_qkv, nullptr, pqkv, 3 * Dd, Dd);
        k_attn_mma<<<dim3(Bb * Hh, Ss / 32), 256, ATTN_SMEM_BYTES>>>();
        k_gemm_mma<<<dim3(Dd / 64, Tt / 128), 256, MMA_SMEM_BYTES>>>(
            pattn, w_out, b_out, px, px, Dd, Dd);
        k_ln<<<Tt, 256>>>(moe_g + (size_t)l * Dd, moe_b + (size_t)l * Dd);
        k_zero16<<<1, 16>>>();
        k_gate<<<Tt / 8, 256>>>(w_gate);
        k_route<<<1, 256>>>();
        k_moe_mma<<<dim3(Dd / 64, (CAPe + 63) / 64, NE), 256, MOE_SMEM_BYTES>>>(w_exp, b_exp);
    }

    k_out<<<(out_size + 255) / 256, 256>>>((float*)d_out, out_size);
}

// round 15
// speedup vs baseline: 1.0083x; 1.0083x over previous
#include <cuda_runtime.h>
#include <math.h>
#include <stdint.h>

#define Bb 2
#define Ss 1024
#define Tt 2048
#define Dd 2048
#define Ll 4
#define NE 16
#define Hh 16
#define DHh 128
#define CAPe 153

typedef unsigned long long u64;

// ---------------- tf32 helpers ----------------------------------------------
__device__ __forceinline__ float tf32r(float x) {
    uint32_t u; asm("cvt.rna.tf32.f32 %0, %1;" : "=r"(u) : "f"(x));
    return __uint_as_float(u);
}
__device__ __forceinline__ void mma8(float* d, const uint32_t* a, const uint32_t* b) {
    asm("mma.sync.aligned.m16n8k8.row.col.f32.tf32.tf32.f32 "
        "{%0,%1,%2,%3}, {%4,%5,%6,%7}, {%8,%9}, {%0,%1,%2,%3};"
        : "+f"(d[0]), "+f"(d[1]), "+f"(d[2]), "+f"(d[3])
        : "r"(a[0]), "r"(a[1]), "r"(a[2]), "r"(a[3]), "r"(b[0]), "r"(b[1]));
}

// ---- dense GEMM smem (stride 36) --------------------------------------------
#define AS_HI 0
#define AS_LO 4608
#define WS_HI 9216
#define WS_LO 11520
#define MMA_SMEM_FLOATS 13824
#define MMA_SMEM_BYTES  (MMA_SMEM_FLOATS * 4)

// ---- MoE BM=64 smem ---------------------------------------------------------
#define MA_HI 0
#define MA_LO 2304
#define MW_HI 4608
#define MW_LO 6912
#define MOE_SMEM_FLOATS 9216
#define MOE_SMEM_BYTES  (MOE_SMEM_FLOATS * 4)

// ---- attention smem ---------------------------------------------------------
#define QHI 0
#define QLO 4224
#define KVHI 8448
#define KVLO 13056
#define SC_  17664
#define PHI  18816
#define PLO  19968
#define MS   21120
#define LS   21152
#define CS   21184
#define ATTN_SMEM_FLOATS 21216
#define ATTN_SMEM_BYTES  (ATTN_SMEM_FLOATS * 4)

// ---------------- scratch ----------------------------------------------------
__device__ float g_x[Tt * Dd];
__device__ float g_xn[Tt * Dd];
__device__ float g_qkv[Tt * 3 * Dd];
__device__ float g_attn[Tt * Dd];
__device__ int   g_expert[Tt];
__device__ float g_prob[Tt];
__device__ float g_probsum[NE];
__device__ int   g_tok[NE * CAPe];
__device__ int   g_cnt[NE];
__device__ float g_aux;

__global__ void k_init() { g_aux = 0.0f; }
__global__ void k_zero16() { if (threadIdx.x < NE) g_probsum[threadIdx.x] = 0.0f; }

// ---------------- embedding gather ------------------------------------------
__global__ void k_embed(const int* __restrict__ tokens, const float* __restrict__ emb) {
    int idx = blockIdx.x * 256 + threadIdx.x;
    int t = idx / Dd;
    int d = idx % Dd;
    g_x[idx] = emb[(size_t)tokens[t] * Dd + d];
}

// ---------------- layernorm (attention side) ---------------------------------
__global__ void k_ln(const float* __restrict__ gamma, const float* __restrict__ beta) {
    int t = blockIdx.x;
    const float* row = g_x + (size_t)t * Dd;
    float s = 0.f, s2 = 0.f;
    for (int d = threadIdx.x; d < Dd; d += 256) {
        float v = row[d];
        s += v; s2 += v * v;
    }
    #pragma unroll
    for (int o = 16; o; o >>= 1) {
        s  += __shfl_xor_sync(0xffffffffu, s, o);
        s2 += __shfl_xor_sync(0xffffffffu, s2, o);
    }
    __shared__ float shs[8], shs2[8];
    __shared__ float smu, srstd;
    int w = threadIdx.x >> 5, ln = threadIdx.x & 31;
    if (ln == 0) { shs[w] = s; shs2[w] = s2; }
    __syncthreads();
    if (threadIdx.x == 0) {
        float a = 0.f, b2 = 0.f;
        #pragma unroll
        for (int i = 0; i < 8; i++) { a += shs[i]; b2 += shs2[i]; }
        float m = a / (float)Dd;
        float var = b2 / (float)Dd - m * m;
        smu = m;
        srstd = rsqrtf(var + 1e-5f);
    }
    __syncthreads();
    float mu = smu, rstd = srstd;
    for (int d = threadIdx.x; d < Dd; d += 256)
        g_xn[(size_t)t * Dd + d] = (row[d] - mu) * rstd * gamma[d] + beta[d];
}

// ---------------- fused MoE LN + gate (warp per token) -----------------------
__global__ void k_lngate(const float* __restrict__ gamma, const float* __restrict__ beta,
                         const float* __restrict__ wg) {
    int warp = threadIdx.x >> 5;
    int lane = threadIdx.x & 31;
    int t = blockIdx.x * 8 + warp;
    __shared__ float bsum[NE];
    if (threadIdx.x < NE) bsum[threadIdx.x] = 0.f;
    __syncthreads();

    const float* row = g_x + (size_t)t * Dd;
    // pass 1: mean/var
    float s = 0.f, s2 = 0.f;
    for (int d = lane; d < Dd; d += 32) {
        float v = row[d];
        s += v; s2 += v * v;
    }
    #pragma unroll
    for (int o = 16; o; o >>= 1) {
        s  += __shfl_xor_sync(0xffffffffu, s, o);
        s2 += __shfl_xor_sync(0xffffffffu, s2, o);
    }
    float mu = s / (float)Dd;
    float rstd = rsqrtf(s2 / (float)Dd - mu * mu + 1e-5f);

    // pass 2: normalize, write g_xn, accumulate gate logits
    float lg[16];
    #pragma unroll
    for (int e = 0; e < 16; e++) lg[e] = 0.f;
    for (int d = lane; d < Dd; d += 32) {
        float v = (row[d] - mu) * rstd * gamma[d] + beta[d];
        g_xn[(size_t)t * Dd + d] = v;
        const float* w = wg + (size_t)d * NE;
        #pragma unroll
        for (int e = 0; e < 16; e++) lg[e] += v * w[e];
    }
    #pragma unroll
    for (int e = 0; e < 16; e++)
        #pragma unroll
        for (int o = 16; o; o >>= 1) lg[e] += __shfl_xor_sync(0xffffffffu, lg[e], o);

    float mx = lg[0];
    #pragma unroll
    for (int e = 1; e < 16; e++) mx = fmaxf(mx, lg[e]);
    float pe[16]; float se = 0.f;
    #pragma unroll
    for (int e = 0; e < 16; e++) { pe[e] = __expf(lg[e] - mx); se += pe[e]; }
    float inv = 1.f / se;

    if (lane == 0) {
        int be = 0; float bl = lg[0];
        #pragma unroll
        for (int e = 1; e < 16; e++) if (lg[e] > bl) { bl = lg[e]; be = e; }
        g_expert[t] = be;
        g_prob[t] = pe[be] * inv;
        #pragma unroll
        for (int e = 0; e < 16; e++) atomicAdd(&bsum[e], pe[e] * inv);
    }
    __syncthreads();
    if (threadIdx.x < NE) atomicAdd(&g_probsum[threadIdx.x], bsum[threadIdx.x]);
}

// ---------------- staging helper --------------------------------------------
__device__ __forceinline__ void split_store(float* sm, int hi_off, int lo_off,
                                            int pos, float4 v) {
    float4 h, l;
    h.x = tf32r(v.x); l.x = tf32r(v.x - h.x);
    h.y = tf32r(v.y); l.y = tf32r(v.y - h.y);
    h.z = tf32r(v.z); l.z = tf32r(v.z - h.z);
    h.w = tf32r(v.w); l.w = tf32r(v.w - h.w);
    *(float4*)(sm + hi_off + pos) = h;
    *(float4*)(sm + lo_off + pos) = l;
}

// ---------------- GEMM mma chunk (BK=32, warp 32x32) -------------------------
__device__ __forceinline__ void mma_chunk(const float* sm, int wr, int wc,
                                          int grp, int qid, float acc[2][4][4]) {
    #pragma unroll
    for (int ks = 0; ks < 4; ks++) {
        int kc = ks * 8;
        uint32_t ahi[2][4], alo[2][4], bhi[4][2], blo[4][2];
        #pragma unroll
        for (int mi = 0; mi < 2; mi++) {
            int rb = wr * 32 + mi * 16;
            int i00 = (rb + grp) * 36 + kc + qid;
            int i10 = (rb + grp + 8) * 36 + kc + qid;
            ahi[mi][0] = *(const uint32_t*)(sm + AS_HI + i00);
            ahi[mi][1] = *(const uint32_t*)(sm + AS_HI + i10);
            ahi[mi][2] = *(const uint32_t*)(sm + AS_HI + i00 + 4);
            ahi[mi][3] = *(const uint32_t*)(sm + AS_HI + i10 + 4);
            alo[mi][0] = *(const uint32_t*)(sm + AS_LO + i00);
            alo[mi][1] = *(const uint32_t*)(sm + AS_LO + i10);
            alo[mi][2] = *(const uint32_t*)(sm + AS_LO + i00 + 4);
            alo[mi][3] = *(const uint32_t*)(sm + AS_LO + i10 + 4);
        }
        #pragma unroll
        for (int ni = 0; ni < 4; ni++) {
            int nb = wc * 32 + ni * 8;
            int i0 = (nb + grp) * 36 + kc + qid;
            bhi[ni][0] = *(const uint32_t*)(sm + WS_HI + i0);
            bhi[ni][1] = *(const uint32_t*)(sm + WS_HI + i0 + 4);
            blo[ni][0] = *(const uint32_t*)(sm + WS_LO + i0);
            blo[ni][1] = *(const uint32_t*)(sm + WS_LO + i0 + 4);
        }
        #pragma unroll
        for (int mi = 0; mi < 2; mi++)
            #pragma unroll
            for (int ni = 0; ni < 4; ni++)
                mma8(acc[mi][ni], ahi[mi], bhi[ni]);
        #pragma unroll
        for (int mi = 0; mi < 2; mi++)
            #pragma unroll
            for (int ni = 0; ni < 4; ni++)
                mma8(acc[mi][ni], ahi[mi], blo[ni]);
        #pragma unroll
        for (int mi = 0; mi < 2; mi++)
            #pragma unroll
            for (int ni = 0; ni < 4; ni++)
                mma8(acc[mi][ni], alo[mi], bhi[ni]);
    }
}

// ---------------- dense GEMM: 3 CTAs/SM, no reg prefetch (R13) ---------------
__global__ void __launch_bounds__(256, 3)
k_gemm_mma(const float* __restrict__ A, const float* __restrict__ W,
           const float* __restrict__ bias, const float* __restrict__ res,
           float* __restrict__ C, int N, int K) {
    extern __shared__ float sm[];
    int tid = threadIdx.x, wid = tid >> 5, lane = tid & 31;
    int grp = lane >> 2, qid = lane & 3;
    int wr = wid & 3, wc = wid >> 2;
    int bm = blockIdx.y * 128, bn = blockIdx.x * 64;

    float acc[2][4][4];
    #pragma unroll
    for (int mi = 0; mi < 2; mi++)
        #pragma unroll
        for (int ni = 0; ni < 4; ni++)
            #pragma unroll
            for (int j = 0; j < 4; j++) acc[mi][ni][j] = 0.f;

    int rA0 = tid >> 3,           cA0 = (tid & 7) * 4;
    int rA1 = (tid + 256) >> 3;
    int rA2 = (tid + 512) >> 3;
    int rA3 = (tid + 768) >> 3;
    int posA0 = rA0 * 36 + cA0, posA1 = rA1 * 36 + cA0;
    int posA2 = rA2 * 36 + cA0, posA3 = rA3 * 36 + cA0;

    const float* ApA0 = A + (size_t)(bm + rA0) * K + cA0;
    const float* ApA1 = A + (size_t)(bm + rA1) * K + cA0;
    const float* ApA2 = A + (size_t)(bm + rA2) * K + cA0;
    const float* ApA3 = A + (size_t)(bm + rA3) * K + cA0;
    const float* WpW0 = W + (size_t)(bn + rA0) * K + cA0;
    const float* WpW1 = W + (size_t)(bn + rA1) * K + cA0;

    int nch = K / 32;
    for (int c = 0; c < nch; c++) {
        int k0 = c * 32;
        split_store(sm, AS_HI, AS_LO, posA0, *(const float4*)(ApA0 + k0));
        split_store(sm, AS_HI, AS_LO, posA1, *(const float4*)(ApA1 + k0));
        split_store(sm, AS_HI, AS_LO, posA2, *(const float4*)(ApA2 + k0));
        split_store(sm, AS_HI, AS_LO, posA3, *(const float4*)(ApA3 + k0));
        split_store(sm, WS_HI, WS_LO, posA0, *(const float4*)(WpW0 + k0));
        split_store(sm, WS_HI, WS_LO, posA1, *(const float4*)(WpW1 + k0));
        __syncthreads();
        mma_chunk(sm, wr, wc, grp, qid, acc);
        __syncthreads();
    }

    #pragma unroll
    for (int mi = 0; mi < 2; mi++) {
        #pragma unroll
        for (int ni = 0; ni < 4; ni++) {
            int r0 = bm + wr * 32 + mi * 16 + grp;
            int r1 = r0 + 8;
            int cc = bn + wc * 32 + ni * 8 + qid * 2;
            float b0 = bias[cc], b1 = bias[cc + 1];
            float v0 = acc[mi][ni][0] + b0, v1 = acc[mi][ni][1] + b1;
            float v2 = acc[mi][ni][2] + b0, v3 = acc[mi][ni][3] + b1;
            if (res) {
                v0 += res[(size_t)r0 * N + cc];
                v1 += res[(size_t)r0 * N + cc + 1];
                v2 += res[(size_t)r1 * N + cc];
                v3 += res[(size_t)r1 * N + cc + 1];
            }
            C[(size_t)r0 * N + cc]     = v0;
            C[(size_t)r0 * N + cc + 1] = v1;
            C[(size_t)r1 * N + cc]     = v2;
            C[(size_t)r1 * N + cc + 1] = v3;
        }
    }
}

// ---------------- MoE GEMM, BM=64 tiles (R13 config: 2 CTA + prefetch) -------
__global__ void __launch_bounds__(256, 2)
k_moe_mma(const float* __restrict__ w_exp, const float* __restrict__ b_exp) {
    int e = blockIdx.z;
    int cnt = g_cnt[e];
    int row0 = blockIdx.y * 64;
    if (row0 >= cnt) return;
    int bn = blockIdx.x * 64;

    extern __shared__ float sm[];
    __shared__ int   toks[64];
    __shared__ float pb[64];
    int tid = threadIdx.x, wid = tid >> 5, lane = tid & 31;
    int grp = lane >> 2, qid = lane & 3;
    int wr = wid & 3, wc = wid >> 2;

    if (tid < 64) {
        int s = row0 + tid;
        if (s < cnt) {
            int t = g_tok[e * CAPe + s];
            toks[tid] = t;
            pb[tid] = g_prob[t];
        } else {
            toks[tid] = -1;
            pb[tid] = 0.f;
        }
    }
    __syncthreads();

    float acc[4][4];
    #pragma unroll
    for (int ni = 0; ni < 4; ni++)
        #pragma unroll
        for (int j = 0; j < 4; j++) acc[ni][j] = 0.f;

    int rS[2], cS[2], posS[2], tA[2];
    #pragma unroll
    for (int j = 0; j < 2; j++) {
        int idx = tid + j * 256;
        rS[j] = idx >> 3; cS[j] = (idx & 7) * 4;
        posS[j] = rS[j] * 36 + cS[j];
        tA[j] = toks[rS[j]];
    }

    const float* Wb = w_exp + (size_t)e * Dd * Dd + (size_t)bn * Dd;
    const int nch = Dd / 32;
    float4 z4 = make_float4(0.f, 0.f, 0.f, 0.f);

    float4 ra[2], rw[2];
    #pragma unroll
    for (int j = 0; j < 2; j++) {
        ra[j] = (tA[j] >= 0) ? *(const float4*)(g_xn + (size_t)tA[j] * Dd + cS[j]) : z4;
        rw[j] = *(const float4*)(Wb + (size_t)rS[j] * Dd + cS[j]);
    }

    for (int c = 0; c < nch; c++) {
        #pragma unroll
        for (int j = 0; j < 2; j++) {
            split_store(sm, MA_HI, MA_LO, posS[j], ra[j]);
            split_store(sm, MW_HI, MW_LO, posS[j], rw[j]);
        }
        __syncthreads();
        if (c + 1 < nch) {
            int k0 = (c + 1) * 32;
            #pragma unroll
            for (int j = 0; j < 2; j++) {
                ra[j] = (tA[j] >= 0) ? *(const float4*)(g_xn + (size_t)tA[j] * Dd + k0 + cS[j]) : z4;
                rw[j] = *(const float4*)(Wb + (size_t)rS[j] * Dd + k0 + cS[j]);
            }
        }
        #pragma unroll
        for (int ks = 0; ks < 4; ks++) {
            int kc = ks * 8;
            uint32_t ah[4], al[4], bh_[4][2], bl_[4][2];
            {
                int i00 = (wr * 16 + grp) * 36 + kc + qid;
                int i10 = i00 + 8 * 36;
                ah[0] = *(const uint32_t*)(sm + MA_HI + i00);
                ah[1] = *(const uint32_t*)(sm + MA_HI + i10);
                ah[2] = *(const uint32_t*)(sm + MA_HI + i00 + 4);
                ah[3] = *(const uint32_t*)(sm + MA_HI + i10 + 4);
                al[0] = *(const uint32_t*)(sm + MA_LO + i00);
                al[1] = *(const uint32_t*)(sm + MA_LO + i10);
                al[2] = *(const uint32_t*)(sm + MA_LO + i00 + 4);
                al[3] = *(const uint32_t*)(sm + MA_LO + i10 + 4);
            }
            #pragma unroll
            for (int ni = 0; ni < 4; ni++) {
                int i0 = (wc * 32 + ni * 8 + grp) * 36 + kc + qid;
                bh_[ni][0] = *(const uint32_t*)(sm + MW_HI + i0);
                bh_[ni][1] = *(const uint32_t*)(sm + MW_HI + i0 + 4);
                bl_[ni][0] = *(const uint32_t*)(sm + MW_LO + i0);
                bl_[ni][1] = *(const uint32_t*)(sm + MW_LO + i0 + 4);
            }
            #pragma unroll
            for (int ni = 0; ni < 4; ni++) mma8(acc[ni], ah, bh_[ni]);
            #pragma unroll
            for (int ni = 0; ni < 4; ni++) mma8(acc[ni], ah, bl_[ni]);
            #pragma unroll
            for (int ni = 0; ni < 4; ni++) mma8(acc[ni], al, bh_[ni]);
        }
        __syncthreads();
    }

    const float* be = b_exp + (size_t)e * Dd;
    int lr0 = wr * 16 + grp;
    int lr1 = lr0 + 8;
    int s0 = row0 + lr0, s1 = row0 + lr1;
    #pragma unroll
    for (int ni = 0; ni < 4; ni++) {
        int cc = bn + wc * 32 + ni * 8 + qid * 2;
        float b0 = be[cc], b1 = be[cc + 1];
        if (s0 < cnt) {
            int t = toks[lr0]; float p = pb[lr0];
            g_x[(size_t)t * Dd + cc]     += p * (acc[ni][0] + b0);
            g_x[(size_t)t * Dd + cc + 1] += p * (acc[ni][1] + b1);
        }
        if (s1 < cnt) {
            int t = toks[lr1]; float p = pb[lr1];
            g_x[(size_t)t * Dd + cc]     += p * (acc[ni][2] + b0);
            g_x[(size_t)t * Dd + cc + 1] += p * (acc[ni][3] + b1);
        }
    }
}

// ---------------- attention via tf32 mma (R12 config) ------------------------
__global__ void __launch_bounds__(256, 2) k_attn_mma() {
    extern __shared__ float sm[];
    int bh = blockIdx.x;
    int b = bh >> 4, h = bh & 15;
    int q0 = blockIdx.y * 32;
    int tid = threadIdx.x, wid = tid >> 5, lane = tid & 31;
    int grp = lane >> 2, qid = lane & 3;
    int wr = wid & 1, wc = wid >> 1;
    int r8 = tid >> 3, dp = tid & 7;

    const float scale = 0.08838834764831845f;

    if (tid < 32) { sm[MS + tid] = -1e30f; sm[LS + tid] = 0.f; }

    {
        const float* src = &g_qkv[(size_t)(b * Ss + q0 + r8) * (3 * Dd) + h * DHh + dp * 16];
        int pos = r8 * 132 + dp * 16;
        #pragma unroll
        for (int j = 0; j < 4; j++)
            split_store(sm, QHI, QLO, pos + j * 4, *(const float4*)(src + j * 4));
    }

    float accO[4][4];
    #pragma unroll
    for (int ni = 0; ni < 4; ni++)
        #pragma unroll
        for (int j = 0; j < 4; j++) accO[ni][j] = 0.f;

    for (int kb = 0; kb < Ss; kb += 32) {
        __syncthreads();
        {
            const float* src = &g_qkv[(size_t)(b * Ss + kb + r8) * (3 * Dd) + Dd + h * DHh + dp * 16];
            int pos = r8 * 132 + dp * 16;
            #pragma unroll
            for (int j = 0; j < 4; j++)
                split_store(sm, KVHI, KVLO, pos + j * 4, *(const float4*)(src + j * 4));
        }
        __syncthreads();

        {
            float accS[4] = {0.f, 0.f, 0.f, 0.f};
            int arow = (wr * 16 + grp) * 132 + qid;
            int brow = (wc * 8 + grp) * 132 + qid;
            #pragma unroll
            for (int kc = 0; kc < 128; kc += 8) {
                uint32_t ah[4], al[4], bh_[2], bl_[2];
                ah[0] = __float_as_uint(sm[QHI + arow + kc]);
                ah[1] = __float_as_uint(sm[QHI + arow + 8 * 132 + kc]);
                ah[2] = __float_as_uint(sm[QHI + arow + kc + 4]);
                ah[3] = __float_as_uint(sm[QHI + arow + 8 * 132 + kc + 4]);
                al[0] = __float_as_uint(sm[QLO + arow + kc]);
                al[1] = __float_as_uint(sm[QLO + arow + 8 * 132 + kc]);
                al[2] = __float_as_uint(sm[QLO + arow + kc + 4]);
                al[3] = __float_as_uint(sm[QLO + arow + 8 * 132 + kc + 4]);
                bh_[0] = __float_as_uint(sm[KVHI + brow + kc]);
                bh_[1] = __float_as_uint(sm[KVHI + brow + kc + 4]);
                bl_[0] = __float_as_uint(sm[KVLO + brow + kc]);
                bl_[1] = __float_as_uint(sm[KVLO + brow + kc + 4]);
                mma8(accS, ah, bh_);
                mma8(accS, ah, bl_);
                mma8(accS, al, bh_);
            }
            int sr = wr * 16 + grp, scc = wc * 8 + qid * 2;
            sm[SC_ + sr * 36 + scc]           = accS[0] * scale;
            sm[SC_ + sr * 36 + scc + 1]       = accS[1] * scale;
            sm[SC_ + (sr + 8) * 36 + scc]     = accS[2] * scale;
            sm[SC_ + (sr + 8) * 36 + scc + 1] = accS[3] * scale;
        }
        __syncthreads();

        {
            const float* src = &g_qkv[(size_t)(b * Ss + kb + r8) * (3 * Dd) + 2 * Dd + h * DHh + dp * 16];
            #pragma unroll
            for (int j = 0; j < 4; j++) {
                float4 v = *(const float4*)(src + j * 4);
                float vv[4] = {v.x, v.y, v.z, v.w};
                #pragma unroll
                for (int c2 = 0; c2 < 4; c2++) {
                    int d = dp * 16 + j * 4 + c2;
                    int kvp = (r8 + ((d >> 4) << 2)) & 31;
                    float hv = tf32r(vv[c2]);
                    sm[KVHI + d * 36 + kvp] = hv;
                    sm[KVLO + d * 36 + kvp] = tf32r(vv[c2] - hv);
                }
            }
        }

        {
            int q = r8;
            float sc4[4];
            float mx = -1e30f;
            #pragma unroll
            for (int c2 = 0; c2 < 4; c2++) {
                sc4[c2] = sm[SC_ + q * 36 + dp * 4 + c2];
                mx = fmaxf(mx, sc4[c2]);
            }
            #pragma unroll
            for (int o = 1; o < 8; o <<= 1)
                mx = fmaxf(mx, __shfl_xor_sync(0xffffffffu, mx, o));
            float mold = sm[MS + q], lold = sm[LS + q];
            float nm = fmaxf(mold, mx);
            float lsum = 0.f;
            #pragma unroll
            for (int c2 = 0; c2 < 4; c2++) {
                float p = __expf(sc4[c2] - nm);
                lsum += p;
                float hv = tf32r(p);
                sm[PHI + q * 36 + dp * 4 + c2] = hv;
                sm[PLO + q * 36 + dp * 4 + c2] = tf32r(p - hv);
            }
            #pragma unroll
            for (int o = 1; o < 8; o <<= 1)
                lsum += __shfl_xor_sync(0xffffffffu, lsum, o);
            if (dp == 0) {
                float corr = __expf(mold - nm);
                sm[MS + q] = nm;
                sm[LS + q] = lold * corr + lsum;
                sm[CS + q] = corr;
            }
        }
        __syncthreads();

        {
            float c0 = sm[CS + wr * 16 + grp];
            float c1 = sm[CS + wr * 16 + grp + 8];
            #pragma unroll
            for (int ni = 0; ni < 4; ni++) {
                accO[ni][0] *= c0; accO[ni][1] *= c0;
                accO[ni][2] *= c1; accO[ni][3] *= c1;
            }
            int arow = (wr * 16 + grp) * 36 + qid;
            #pragma unroll
            for (int kc = 0; kc < 32; kc += 8) {
                uint32_t ah[4], al[4];
                ah[0] = __float_as_uint(sm[PHI + arow + kc]);
                ah[1] = __float_as_uint(sm[PHI + arow + 8 * 36 + kc]);
                ah[2] = __float_as_uint(sm[PHI + arow + kc + 4]);
                ah[3] = __float_as_uint(sm[PHI + arow + 8 * 36 + kc + 4]);
                al[0] = __float_as_uint(sm[PLO + arow + kc]);
                al[1] = __float_as_uint(sm[PLO + arow + 8 * 36 + kc]);
                al[2] = __float_as_uint(sm[PLO + arow + kc + 4]);
                al[3] = __float_as_uint(sm[PLO + arow + 8 * 36 + kc + 4]);
                #pragma unroll
                for (int ni = 0; ni < 4; ni++) {
                    int n = wc * 32 + ni * 8 + grp;
                    int off = (n >> 4) << 2;
                    int k0i = (kc + qid + off) & 31;
                    int k1i = (kc + qid + 4 + off) & 31;
                    uint32_t bh_[2], bl_[2];
                    bh_[0] = __float_as_uint(sm[KVHI + n * 36 + k0i]);
                    bh_[1] = __float_as_uint(sm[KVHI + n * 36 + k1i]);
                    bl_[0] = __float_as_uint(sm[KVLO + n * 36 + k0i]);
                    bl_[1] = __float_as_uint(sm[KVLO + n * 36 + k1i]);
                    mma8(accO[ni], ah, bh_);
                    mma8(accO[ni], ah, bl_);
                    mma8(accO[ni], al, bh_);
                }
            }
        }
    }

    {
        float li0 = 1.f / sm[LS + wr * 16 + grp];
        float li1 = 1.f / sm[LS + wr * 16 + grp + 8];
        size_t t0 = (size_t)(b * Ss + q0 + wr * 16 + grp) * Dd + h * DHh;
        size_t t1 = (size_t)(b * Ss + q0 + wr * 16 + grp + 8) * Dd + h * DHh;
        #pragma unroll
        for (int ni = 0; ni < 4; ni++) {
            int col = wc * 32 + ni * 8 + qid * 2;
            g_attn[t0 + col]     = accO[ni][0] * li0;
            g_attn[t0 + col + 1] = accO[ni][1] * li0;
            g_attn[t1 + col]     = accO[ni][2] * li1;
            g_attn[t1 + col + 1] = accO[ni][3] * li1;
        }
    }
}

// ---------------- routing ---------------------------------------------------
__global__ void k_route() {
    __shared__ int sh_e[Tt];
    __shared__ int cnts[256][NE];
    __shared__ int tot[NE];
    int tid = threadIdx.x;
    for (int i = tid; i < Tt; i += 256) sh_e[i] = g_expert[i];
    #pragma unroll
    for (int e = 0; e < NE; e++) cnts[tid][e] = 0;
    __syncthreads();
    for (int i = 0; i < 8; i++) {
        int e = sh_e[tid * 8 + i];
        cnts[tid][e]++;
    }
    __syncthreads();
    if (tid < NE) {
        int run = 0;
        for (int i = 0; i < 256; i++) {
            int c = cnts[i][tid];
            cnts[i][tid] = run;
            run += c;
        }
        tot[tid] = run;
        g_cnt[tid] = (run < CAPe) ? run : CAPe;
    }
    __syncthreads();
    for (int i = 0; i < 8; i++) {
        int t = tid * 8 + i;
        int e = sh_e[t];
        int r = cnts[tid][e]++;
        if (r < CAPe) g_tok[e * CAPe + r] = t;
    }
    if (tid == 0) {
        float a = 0.f;
        for (int e = 0; e < NE; e++) a += (float)tot[e] * g_probsum[e];
        g_aux += a * ((float)NE / ((float)Tt * (float)Tt));
    }
}

// ---------------- output ----------------------------------------------------
__global__ void k_out(float* __restrict__ out, int n) {
    int idx = blockIdx.x * 256 + threadIdx.x;
    if (idx < n) {
        if (idx < Tt * Dd) out[idx] = g_x[idx];
        else out[idx] = g_aux;
    }
}

// ---------------- launch ----------------------------------------------------
extern "C" void kernel_launch(void* const* d_in, const int* in_sizes, int n_in,
                              void* d_out, int out_size) {
    const int*   tokens = (const int*)d_in[0];
    const float* emb    = (const float*)d_in[1];
    const float* w_qkv  = (const float*)d_in[2];
    const float* b_qkv  = (const float*)d_in[3];
    const float* w_out  = (const float*)d_in[4];
    const float* b_out  = (const float*)d_in[5];
    const float* attn_g = (const float*)d_in[6];
    const float* attn_b = (const float*)d_in[7];
    const float* moe_g  = (const float*)d_in[8];
    const float* moe_b  = (const float*)d_in[9];
    const float* w_gate = (const float*)d_in[10];
    const float* w_exp  = (const float*)d_in[11];
    const float* b_exp  = (const float*)d_in[12];

    float *px, *pxn, *pqkv, *pattn;
    cudaGetSymbolAddress((void**)&px, g_x);
    cudaGetSymbolAddress((void**)&pxn, g_xn);
    cudaGetSymbolAddress((void**)&pqkv, g_qkv);
    cudaGetSymbolAddress((void**)&pattn, g_attn);

    cudaFuncSetAttribute(k_gemm_mma, cudaFuncAttributeMaxDynamicSharedMemorySize, MMA_SMEM_BYTES);
    cudaFuncSetAttribute(k_moe_mma, cudaFuncAttributeMaxDynamicSharedMemorySize, MOE_SMEM_BYTES);
    cudaFuncSetAttribute(k_attn_mma, cudaFuncAttributeMaxDynamicSharedMemorySize, ATTN_SMEM_BYTES);

    k_init<<<1, 1>>>();
    k_embed<<<(Tt * Dd) / 256, 256>>>(tokens, emb);

    for (int l = 0; l < Ll; l++) {
        k_ln<<<Tt, 256>>>(attn_g + (size_t)l * Dd, attn_b + (size_t)l * Dd);
        k_gemm_mma<<<dim3((3 * Dd) / 64, Tt / 128), 256, MMA_SMEM_BYTES>>>(
            pxn, w_qkv, b_qkv, nullptr, pqkv, 3 * Dd, Dd);
        k_attn_mma<<<dim3(Bb * Hh, Ss / 32), 256, ATTN_SMEM_BYTES>>>();
        k_gemm_mma<<<dim3(Dd / 64, Tt / 128), 256, MMA_SMEM_BYTES>>>(
            pattn, w_out, b_out, px, px, Dd, Dd);
        k_zero16<<<1, 16>>>();
        k_lngate<<<Tt / 8, 256>>>(moe_g + (size_t)l * Dd, moe_b + (size_t)l * Dd, w_gate);
        k_route<<<1, 256>>>();
        k_moe_mma<<<dim3(Dd / 64, (CAPe + 63) / 64, NE), 256, MOE_SMEM_BYTES>>>(w_exp, b_exp);
    }

    k_out<<<(out_size + 255) / 256, 256>>>((float*)d_out, out_size);
}